// round 15
// baseline (speedup 1.0000x reference)
#include <cuda_runtime.h>
#include <cuda_fp16.h>
#include <math.h>
#include <stdint.h>

// Problem constants
#define Bb   64
#define Ss   128
#define Hh   768
#define Aa   512
#define COn  100
#define TnK  5
#define T1K  6
#define Nn   64
#define SCn  12
#define MSZ  (Bb*Ss*Hh)      // 6291456
#define M1   (Bb*Ss)         // 8192

#define NG_PAD 2560          // 2400 real, padded to 10*256
#define NA_PAD 1280
#define MG     (TnK*M1)      // 40960

#define YG_TILES (10 * 320)  // 3200   (256-wide tiles)
#define YA_TILES (5 * 64)    // 320

// ---------------------------------------------------------------------------
// Scratch (static device globals — allocation-free)
// ---------------------------------------------------------------------------
__device__ __half g_xf[MSZ];
__device__ __half g_f1f[T1K * Aa * Hh];
__device__ __half g_f2f[T1K * Hh * Aa];
__device__ __half g_h1f[T1K * M1 * Aa];
__device__ __half g_h2f[T1K * MSZ];
__device__ __half g_sqf[T1K * MSZ];
__device__ __half g_Wgh[NG_PAD * Hh];
__device__ __half g_Wah[NA_PAD * Hh];
__device__ __half g_Ygh[(long)MG * NG_PAD];
__device__ __half g_Yah[(long)M1 * NA_PAD];
__device__ float g_rwT[(long)Nn * T1K * SCn * 300];
__device__ float g_aspf[Bb * 3 * COn];
__device__ float g_asp[Bb * COn];
__device__ float g_z[TnK * Bb * 3 * COn];
__device__ float g_vote[Nn * Bb * SCn];

// ---------------------------------------------------------------------------
// helpers
// ---------------------------------------------------------------------------
__device__ __forceinline__ void mma_fp16(float* c, const uint32_t* a, const uint32_t* b)
{
    asm volatile(
        "mma.sync.aligned.m16n8k16.row.col.f32.f16.f16.f32 "
        "{%0,%1,%2,%3}, {%4,%5,%6,%7}, {%8,%9}, {%0,%1,%2,%3};"
        : "+f"(c[0]), "+f"(c[1]), "+f"(c[2]), "+f"(c[3])
        : "r"(a[0]), "r"(a[1]), "r"(a[2]), "r"(a[3]), "r"(b[0]), "r"(b[1]));
}

__device__ __forceinline__ void ldsm_x4(uint32_t* r, uint32_t addr)
{
    asm volatile("ldmatrix.sync.aligned.m8n8.x4.shared.b16 {%0,%1,%2,%3}, [%4];"
                 : "=r"(r[0]), "=r"(r[1]), "=r"(r[2]), "=r"(r[3]) : "r"(addr));
}

__device__ __forceinline__ void ldsm_x2(uint32_t* r, uint32_t addr)
{
    asm volatile("ldmatrix.sync.aligned.m8n8.x2.shared.b16 {%0,%1}, [%2];"
                 : "=r"(r[0]), "=r"(r[1]) : "r"(addr));
}

__device__ __forceinline__ void cp16(void* sdst, const void* gsrc)
{
    uint32_t s = (uint32_t)__cvta_generic_to_shared(sdst);
    asm volatile("cp.async.cg.shared.global [%0], [%1], 16;" :: "r"(s), "l"(gsrc));
}
#define CP_COMMIT() asm volatile("cp.async.commit_group;" ::: "memory")
#define CP_WAIT0()  asm volatile("cp.async.wait_group 0;" ::: "memory")
#define CP_WAIT1()  asm volatile("cp.async.wait_group 1;" ::: "memory")

// 128x256 tile, KC=32, RSTR=40, 3-stage pipeline, 512 threads
#define KC       32
#define RSTR     40
#define A_ELE    (128 * RSTR)           // 5120 halfs
#define B_ELE    (256 * RSTR)           // 10240 halfs
#define STG_ELE  (A_ELE + B_ELE)        // 15360 halfs = 30720 B
#define NSTG     3
#define SMEM_CV  (NSTG * STG_ELE * 2)   // 92160 bytes

// ---------------------------------------------------------------------------
// GEMM core — 128x256 tile, 16 warps (4x4), ldmatrix, 3-stage cp.async
// ---------------------------------------------------------------------------
template<int BIASRELU>
__device__ __forceinline__ void gemm_body(
    __half* smh, const __half* __restrict__ A, const __half* __restrict__ B,
    int N, int Kd, int m0, int n0,
    const float* __restrict__ bias, __half* __restrict__ Ch, long co)
{
    int tid = threadIdx.x, lane = tid & 31, wid = tid >> 5;
    int wm = wid >> 2, wn = wid & 3;         // 4x4 warps; warp tile 32 rows x 64 cols
    int gid = lane >> 2, tig = lane & 3;

    // ldmatrix per-lane offsets (halfs, relative to tile base)
    int a_off = (wm * 32 + (lane & 15)) * RSTR + (lane >> 4) * 8;       // + mt*16*RSTR + kk
    int b_off = (wn * 64 + (lane & 7)) * RSTR + ((lane >> 3) & 1) * 8;  // + nt*8*RSTR + kk

    uint32_t smh_s = (uint32_t)__cvta_generic_to_shared(smh);

    auto issue = [&](int c) {
        __half* base = smh + (c % NSTG) * STG_ELE;
        int k0 = c * KC;
        #pragma unroll
        for (int it = 0; it < 3; it++) {
            int i = tid + it * 512;          // 0..1535 over 384 rows x 4 segs
            int row = i >> 2, cseg = (i & 3) * 8;
            if (row < 128) {
                cp16(base + row * RSTR + cseg,
                     A + (long)(m0 + row) * Kd + k0 + cseg);
            } else {
                int rb = row - 128;
                cp16(base + A_ELE + rb * RSTR + cseg,
                     B + (long)(n0 + rb) * Kd + k0 + cseg);
            }
        }
        CP_COMMIT();
    };

    float acc[2][8][4] = {};
    int nch = Kd / KC;

    issue(0);
    issue(1);

    for (int c = 0; c < nch; c++) {
        if (c + 1 == nch) CP_WAIT0(); else CP_WAIT1();
        __syncthreads();
        if (c + 2 < nch) issue(c + 2);

        uint32_t As_s = smh_s + (uint32_t)((c % NSTG) * STG_ELE) * 2u;
        uint32_t Bs_s = As_s + A_ELE * 2u;

        #pragma unroll
        for (int kk = 0; kk < KC; kk += 16) {
            uint32_t bf[8][2];
            #pragma unroll
            for (int nt = 0; nt < 8; nt++)
                ldsm_x2(bf[nt], Bs_s + (uint32_t)(b_off + nt * 8 * RSTR + kk) * 2u);
            #pragma unroll
            for (int mt = 0; mt < 2; mt++) {
                uint32_t ah[4];
                ldsm_x4(ah, As_s + (uint32_t)(a_off + mt * 16 * RSTR + kk) * 2u);
                #pragma unroll
                for (int nt = 0; nt < 8; nt++)
                    mma_fp16(acc[mt][nt], ah, bf[nt]);
            }
        }
    }

    #pragma unroll
    for (int mt = 0; mt < 2; mt++) {
        long m = m0 + wm * 32 + mt * 16 + gid;
        #pragma unroll
        for (int nt = 0; nt < 8; nt++) {
            int col = n0 + wn * 64 + nt * 8 + tig * 2;
            float v00 = acc[mt][nt][0], v01 = acc[mt][nt][1];
            float v10 = acc[mt][nt][2], v11 = acc[mt][nt][3];
            if (BIASRELU) {
                float b0 = bias[col], b1 = bias[col + 1];
                v00 = fmaxf(v00 + b0, 0.f); v01 = fmaxf(v01 + b1, 0.f);
                v10 = fmaxf(v10 + b0, 0.f); v11 = fmaxf(v11 + b1, 0.f);
            }
            *(__half2*)(Ch + co + m * N + col)       = __floats2half2_rn(v00, v01);
            *(__half2*)(Ch + co + (m + 8) * N + col) = __floats2half2_rn(v10, v11);
        }
    }
}

// fc GEMM (bias+relu), z-batched; N-tile 256
__global__ void __launch_bounds__(512, 1)
mma_fc(const __half* __restrict__ A, const __half* __restrict__ B,
       const float* __restrict__ bias, __half* __restrict__ Ch,
       int N, int Kd, long sA, long sW, long sB, long sC)
{
    extern __shared__ __half smh[];
    gemm_body<1>(smh, A + blockIdx.z * sA, B + blockIdx.z * sW,
                 N, Kd, blockIdx.y * 128, blockIdx.x * 256,
                 bias + blockIdx.z * sB, Ch, blockIdx.z * sC);
}

// combined conv GEMM (Yg tiles then Ya tiles), no bias
__global__ void __launch_bounds__(512, 1)
mma_conv(const __half* __restrict__ sq, const __half* __restrict__ Wg,
         const __half* __restrict__ Wa, __half* __restrict__ Yg,
         __half* __restrict__ Ya)
{
    extern __shared__ __half smh[];
    int bid = blockIdx.x;
    if (bid < YG_TILES) {
        gemm_body<0>(smh, sq + (long)MSZ, Wg, NG_PAD, Hh,
                     (bid / 10) * 128, (bid % 10) * 256, nullptr, Yg, 0L);
    } else {
        int b2 = bid - YG_TILES;
        gemm_body<0>(smh, sq, Wa, NA_PAD, Hh,
                     (b2 / 5) * 128, (b2 % 5) * 256, nullptr, Ya, 0L);
    }
}

// ===========================================================================
// prep_all: all operand preparation in one launch (segmented grid)
// ===========================================================================
#define W0 ((long)MSZ / 2)
#define W1 ((long)T1K * Aa * Hh / 2)
#define W2 ((long)T1K * Hh * Aa / 2)
#define W3 ((long)NG_PAD * Hh)
#define W4 ((long)NA_PAD * Hh)
#define W5 ((long)Nn * T1K * SCn * 300)
#define WTOT (W0 + W1 + W2 + W3 + W4 + W5)

__device__ __forceinline__ void decode_kg(int kg, int& K, int& k)
{
    if (kg < 3)      { K = 3; k = kg; }
    else if (kg < 7) { K = 4; k = kg - 3; }
    else             { K = 5; k = kg - 7; }
}

__global__ void prep_all(const float* __restrict__ x,
                         const float* __restrict__ f1w, const float* __restrict__ f2w,
                         const float* __restrict__ c1w3, const float* __restrict__ c1w4,
                         const float* __restrict__ c1w5, const float* __restrict__ c2w3,
                         const float* __restrict__ c2w4, const float* __restrict__ c2w5,
                         const float* __restrict__ c3w3, const float* __restrict__ c3w4,
                         const float* __restrict__ c3w5, const float* __restrict__ rw)
{
    long g = (long)blockIdx.x * 256 + threadIdx.x;
    if (g < W0) {
        long i = g * 2;
        float2 v = *(const float2*)(x + i);
        *(__half2*)(g_xf + i) = __floats2half2_rn(v.x, v.y);
        return;
    }
    g -= W0;
    if (g < W1) {
        long i = g * 2;
        float2 v = *(const float2*)(f1w + i);
        *(__half2*)(g_f1f + i) = __floats2half2_rn(v.x, v.y);
        return;
    }
    g -= W1;
    if (g < W2) {
        long i = g * 2;
        float2 v = *(const float2*)(f2w + i);
        *(__half2*)(g_f2f + i) = __floats2half2_rn(v.x, v.y);
        return;
    }
    g -= W2;
    if (g < W3) {
        int ch = (int)(g / Hh), h = (int)(g % Hh);
        float v = 0.f;
        if (ch < 2400) {
            int kg = ch / 200, r = ch % 200;
            int conv = r / 100, cco = r % 100;
            int K, k; decode_kg(kg, K, k);
            const float* w;
            if (conv == 0) w = (K == 3) ? c1w3 : (K == 4) ? c1w4 : c1w5;
            else           w = (K == 3) ? c2w3 : (K == 4) ? c2w4 : c2w5;
            v = w[(long)cco * Hh * K + h * K + k];
        }
        g_Wgh[g] = __float2half_rn(v);
        return;
    }
    g -= W3;
    if (g < W4) {
        int ch = (int)(g / Hh), h = (int)(g % Hh);
        float v = 0.f;
        if (ch < 1200) {
            int kg = ch / 100, cco = ch % 100;
            int K, k; decode_kg(kg, K, k);
            const float* w = (K == 3) ? c3w3 : (K == 4) ? c3w4 : c3w5;
            v = w[(long)cco * Hh * K + h * K + k];
        }
        g_Wah[g] = __float2half_rn(v);
        return;
    }
    g -= W4;
    if (g < W5) {
        int c = (int)(g % 300);
        long row = g / 300;
        int s = (int)(row % 12);
        long ni = row / 12;
        g_rwT[g] = rw[(ni * 300 + c) * 12 + s];
    }
}

// ===========================================================================
// squash: vectorized, 8 elems/thread
// ===========================================================================
__global__ void squash_kernel()
{
    long i = ((long)blockIdx.x * 256 + threadIdx.x) * 8;
    if (i >= MSZ) return;
    float v[6][8];
    #pragma unroll
    for (int j = 0; j < 6; j++) {
        int src = (j == 0) ? 5 : j - 1;
        uint4 p = *(const uint4*)(g_h2f + (long)src * MSZ + i);
        const __half2* hp = (const __half2*)&p;
        #pragma unroll
        for (int q = 0; q < 4; q++) {
            float2 f = __half22float2(hp[q]);
            v[j][q * 2] = f.x; v[j][q * 2 + 1] = f.y;
        }
    }
    #pragma unroll
    for (int e = 0; e < 8; e++) {
        float sq = 1e-16f;
        #pragma unroll
        for (int j = 0; j < 6; j++) sq += v[j][e] * v[j][e];
        float sc = sqrtf(sq) / (1.f + sq);
        #pragma unroll
        for (int j = 0; j < 6; j++) v[j][e] *= sc;
    }
    #pragma unroll
    for (int j = 0; j < 6; j++) {
        uint4 p;
        __half2* hp = (__half2*)&p;
        #pragma unroll
        for (int q = 0; q < 4; q++)
            hp[q] = __floats2half2_rn(v[j][q * 2], v[j][q * 2 + 1]);
        *(uint4*)(g_sqf + (long)j * MSZ + i) = p;
    }
}

// ===========================================================================
// Fused aspect epilogue + fca
// ===========================================================================
__global__ void aspect_fca(const float* __restrict__ b3, const float* __restrict__ b4,
                           const float* __restrict__ b5,
                           const float* __restrict__ fw, const float* __restrict__ fb)
{
    __shared__ float red[4 * 300];
    __shared__ float aspf_s[300];
    int b = blockIdx.x, t = threadIdx.x;

    if (t < 600) {
        int lg = t / 150, r = t % 150;
        int g = r / 50, co0 = (r % 50) * 2;
        int K = 3 + g;
        int base = (g == 0) ? 0 : (g == 1) ? 3 : 7;
        int pad = K - 2;
        const float* bias = (g == 0) ? b3 : (g == 1) ? b4 : b5;
        float bb0 = bias[co0], bb1 = bias[co0 + 1];
        int Lout = 125 + K;
        int l0 = lg * 33, l1 = min(Lout, l0 + 33);
        float best0 = 0.f, best1 = 0.f;
        for (int l = l0; l < l1; l++) {
            float s0 = bb0, s1 = bb1;
            #pragma unroll 5
            for (int k = 0; k < K; k++) {
                int ss = l + k - pad;
                if (ss >= 0 && ss < Ss) {
                    __half2 h = *(const __half2*)(g_Yah + ((long)b * Ss + ss) * NA_PAD + (base + k) * 100 + co0);
                    float2 f = __half22float2(h);
                    s0 += f.x; s1 += f.y;
                }
            }
            best0 = fmaxf(best0, s0);
            best1 = fmaxf(best1, s1);
        }
        red[lg * 300 + g * 100 + co0]     = best0;
        red[lg * 300 + g * 100 + co0 + 1] = best1;
    }
    __syncthreads();
    if (t < 300) {
        float m = fmaxf(fmaxf(red[t], red[300 + t]), fmaxf(red[600 + t], red[900 + t]));
        aspf_s[t] = m;
        g_aspf[b * 300 + t] = m;
    }
    __syncthreads();
    if (t < COn) {
        float s = fb[t];
        for (int c = 0; c < 300; c++) s += aspf_s[c] * fw[t * 300 + c];
        g_asp[b * COn + t] = s;
    }
}

// ===========================================================================
// Gated epilogue
// ===========================================================================
__global__ void gated_epi(const float* __restrict__ b13, const float* __restrict__ b14,
                          const float* __restrict__ b15, const float* __restrict__ b23,
                          const float* __restrict__ b24, const float* __restrict__ b25)
{
    __shared__ float red[4 * 300];
    int i = blockIdx.x, t = threadIdx.x;
    int b = i & 63;

    if (t < 600) {
        int lg = t / 150, r = t % 150;
        int g = r / 50, co0 = (r % 50) * 2;
        int K = 3 + g;
        int base = (g == 0) ? 0 : (g == 1) ? 3 : 7;
        const float* bias1 = (g == 0) ? b13 : (g == 1) ? b14 : b15;
        const float* bias2 = (g == 0) ? b23 : (g == 1) ? b24 : b25;
        float c1b0 = bias1[co0], c1b1 = bias1[co0 + 1];
        float c2b0 = bias2[co0]     + g_asp[b * COn + co0];
        float c2b1 = bias2[co0 + 1] + g_asp[b * COn + co0 + 1];
        int Lout = Ss - K + 1;
        int l0 = lg * 32, l1 = min(Lout, l0 + 32);
        float best0 = -1e30f, best1 = -1e30f;
        for (int l = l0; l < l1; l++) {
            float s10 = c1b0, s11 = c1b1, s20 = c2b0, s21 = c2b1;
            #pragma unroll 5
            for (int k = 0; k < K; k++) {
                long row = (long)i * Ss + l + k;
                __half2 ha = *(const __half2*)(g_Ygh + row * NG_PAD + (base + k) * 200 + co0);
                __half2 hb = *(const __half2*)(g_Ygh + row * NG_PAD + (base + k) * 200 + 100 + co0);
                float2 fa = __half22float2(ha);
                float2 fbv = __half22float2(hb);
                s10 += fa.x;  s11 += fa.y;
                s20 += fbv.x; s21 += fbv.y;
            }
            float v0 = tanhf(s10) * fmaxf(s20, 0.f);
            float v1 = tanhf(s11) * fmaxf(s21, 0.f);
            best0 = fmaxf(best0, v0);
            best1 = fmaxf(best1, v1);
        }
        red[lg * 300 + g * 100 + co0]     = best0;
        red[lg * 300 + g * 100 + co0 + 1] = best1;
    }
    __syncthreads();
    if (t < 300)
        g_z[i * 300 + t] = fmaxf(fmaxf(red[t], red[300 + t]), fmaxf(red[600 + t], red[900 + t]));
}

// ===========================================================================
// Fused priors + routing
// ===========================================================================
__global__ void priors_routing()
{
    __shared__ float cap[1800];
    __shared__ float pri[72];
    int b = blockIdx.x, n = blockIdx.y, tid = threadIdx.x;
    for (int idx = tid; idx < 1800; idx += 128) {
        int i = idx / 300, c = idx % 300;
        cap[idx] = (i == 0) ? g_aspf[b * 300 + c] : g_z[((i - 1) * Bb + b) * 300 + c];
    }
    __syncthreads();
    if (tid < 72) {
        int i = tid / 12, s = tid % 12;
        const float4* rp = (const float4*)(g_rwT + ((long)(n * 6 + i) * 12 + s) * 300);
        const float* cp = &cap[i * 300];
        float acc = 0.f;
        #pragma unroll 5
        for (int c4 = 0; c4 < 75; c4++) {
            float4 r4 = rp[c4];
            acc += cp[c4 * 4]     * r4.x + cp[c4 * 4 + 1] * r4.y
                 + cp[c4 * 4 + 2] * r4.z + cp[c4 * 4 + 3] * r4.w;
        }
        pri[tid] = acc;
    }
    __syncthreads();
    if (tid == 0) {
        float logits[6] = {0, 0, 0, 0, 0, 0};
        float vote[12];
        #pragma unroll
        for (int it = 0; it < 3; it++) {
            float mx = logits[0];
            #pragma unroll
            for (int i = 1; i < 6; i++) mx = fmaxf(mx, logits[i]);
            float e[6], se = 0.f;
            #pragma unroll
            for (int i = 0; i < 6; i++) { e[i] = expf(logits[i] - mx); se += e[i]; }
            float inv = 1.f / se;
            #pragma unroll
            for (int s = 0; s < 12; s++) {
                float v = 0.f;
                #pragma unroll
                for (int i = 0; i < 6; i++) v += e[i] * pri[i * 12 + s];
                vote[s] = v * inv;
            }
            if (it < 2) {
                float sq = 1e-16f;
                #pragma unroll
                for (int s = 0; s < 12; s++) sq += vote[s] * vote[s];
                float sc = sqrtf(sq) / (1.f + sq);
                #pragma unroll
                for (int i = 0; i < 6; i++) {
                    float d = 0.f;
                    #pragma unroll
                    for (int s = 0; s < 12; s++) d += pri[i * 12 + s] * vote[s];
                    logits[i] += d * sc;
                }
            }
        }
        #pragma unroll
        for (int s = 0; s < 12; s++)
            g_vote[(n * Bb + b) * 12 + s] = vote[s];
    }
}

// ===========================================================================
// final residual add, float4 vectorized
// ===========================================================================
__global__ void final_kernel(const float* __restrict__ x, float* __restrict__ out)
{
    long idx = ((long)blockIdx.x * 256 + threadIdx.x) * 4;
    if (idx >= MSZ) return;
    float4 xv = *(const float4*)(x + idx);
    uint2 hp = *(const uint2*)(g_h2f + (long)5 * MSZ + idx);
    const __half2* hh = (const __half2*)&hp;
    float2 h0 = __half22float2(hh[0]);
    float2 h1 = __half22float2(hh[1]);
    int b = (int)(idx / (Ss * Hh));
    int h = (int)(idx % Hh);
    float4 vv = *(const float4*)(g_vote + b * Hh + h);
    float4 o;
    o.x = xv.x + h0.x + vv.x;
    o.y = xv.y + h0.y + vv.y;
    o.z = xv.z + h1.x + vv.z;
    o.w = xv.w + h1.y + vv.w;
    *(float4*)(out + idx) = o;
}

// ===========================================================================
extern "C" void kernel_launch(void* const* d_in, const int* in_sizes, int n_in,
                              void* d_out, int out_size)
{
    const float* x     = (const float*)d_in[0];
    const float* fc1_w = (const float*)d_in[1];
    const float* fc1_b = (const float*)d_in[2];
    const float* fc2_w = (const float*)d_in[3];
    const float* fc2_b = (const float*)d_in[4];
    const float* c1_w3 = (const float*)d_in[5];
    const float* c1_b3 = (const float*)d_in[6];
    const float* c1_w4 = (const float*)d_in[7];
    const float* c1_b4 = (const float*)d_in[8];
    const float* c1_w5 = (const float*)d_in[9];
    const float* c1_b5 = (const float*)d_in[10];
    const float* c2_w3 = (const float*)d_in[11];
    const float* c2_b3 = (const float*)d_in[12];
    const float* c2_w4 = (const float*)d_in[13];
    const float* c2_b4 = (const float*)d_in[14];
    const float* c2_w5 = (const float*)d_in[15];
    const float* c2_b5 = (const float*)d_in[16];
    const float* c3_w3 = (const float*)d_in[17];
    const float* c3_b3 = (const float*)d_in[18];
    const float* c3_w4 = (const float*)d_in[19];
    const float* c3_b4 = (const float*)d_in[20];
    const float* c3_w5 = (const float*)d_in[21];
    const float* c3_b5 = (const float*)d_in[22];
    const float* fca_w = (const float*)d_in[23];
    const float* fca_b = (const float*)d_in[24];
    const float* rw    = (const float*)d_in[25];
    float* out = (float*)d_out;

    __half *p_xf, *p_f1f, *p_f2f, *p_h1f, *p_h2f, *p_sqf, *p_Wgh, *p_Wah, *p_Ygh, *p_Yah;
    cudaGetSymbolAddress((void**)&p_xf,  g_xf);
    cudaGetSymbolAddress((void**)&p_f1f, g_f1f);
    cudaGetSymbolAddress((void**)&p_f2f, g_f2f);
    cudaGetSymbolAddress((void**)&p_h1f, g_h1f);
    cudaGetSymbolAddress((void**)&p_h2f, g_h2f);
    cudaGetSymbolAddress((void**)&p_sqf, g_sqf);
    cudaGetSymbolAddress((void**)&p_Wgh, g_Wgh);
    cudaGetSymbolAddress((void**)&p_Wah, g_Wah);
    cudaGetSymbolAddress((void**)&p_Ygh, g_Ygh);
    cudaGetSymbolAddress((void**)&p_Yah, g_Yah);

    cudaFuncSetAttribute(mma_fc,   cudaFuncAttributeMaxDynamicSharedMemorySize, SMEM_CV);
    cudaFuncSetAttribute(mma_conv, cudaFuncAttributeMaxDynamicSharedMemorySize, SMEM_CV);

    // 0) all operand prep in one launch
    prep_all<<<(int)((WTOT + 255) / 256), 256>>>(
        x, fc1_w, fc2_w, c1_w3, c1_w4, c1_w5, c2_w3, c2_w4, c2_w5,
        c3_w3, c3_w4, c3_w5, rw);

    // 1) h1 = relu(x @ fc1_w^T + b) -> fp16   (N-tile 256)
    mma_fc<<<dim3(Aa / 256, M1 / 128, T1K), 512, SMEM_CV>>>(
        p_xf, p_f1f, fc1_b, p_h1f,
        Aa, Hh, 0L, (long)Aa * Hh, (long)Aa, (long)M1 * Aa);

    // 2) h2 = relu(h1 @ fc2_w^T + b) -> fp16
    mma_fc<<<dim3(Hh / 256, M1 / 128, T1K), 512, SMEM_CV>>>(
        p_h1f, p_f2f, fc2_b, p_h2f,
        Hh, Aa, (long)M1 * Aa, (long)Hh * Aa, (long)Hh, (long)M1 * Hh);

    // 3) squash -> fp16 capsules
    squash_kernel<<<(MSZ / 8 + 255) / 256, 256>>>();

    // 4) combined conv GEMMs (Yg + Ya in one launch)
    mma_conv<<<YG_TILES + YA_TILES, 512, SMEM_CV>>>(p_sqf, p_Wgh, p_Wah, p_Ygh, p_Yah);

    // 5) epilogues
    aspect_fca<<<Bb, 640>>>(c3_b3, c3_b4, c3_b5, fca_w, fca_b);
    gated_epi<<<TnK * Bb, 640>>>(c1_b3, c1_b4, c1_b5, c2_b3, c2_b4, c2_b5);

    // 6) fused priors + routing
    priors_routing<<<dim3(Bb, Nn), 128>>>();

    // 7) residual add
    final_kernel<<<(MSZ / 4 + 255) / 256, 256>>>(x, out);
}

// round 16
// speedup vs baseline: 1.1518x; 1.1518x over previous
#include <cuda_runtime.h>
#include <cuda_fp16.h>
#include <math.h>
#include <stdint.h>

// Problem constants
#define Bb   64
#define Ss   128
#define Hh   768
#define Aa   512
#define COn  100
#define TnK  5
#define T1K  6
#define Nn   64
#define SCn  12
#define MSZ  (Bb*Ss*Hh)      // 6291456
#define M1   (Bb*Ss)         // 8192

#define NG_PAD 2432
#define NA_PAD 1280
#define MG     (TnK*M1)      // 40960

#define YG_TILES (19 * 320)  // 6080
#define YA_TILES (10 * 64)   // 640

// ---------------------------------------------------------------------------
// Scratch (static device globals — allocation-free)
// ---------------------------------------------------------------------------
__device__ __half g_xf[MSZ];
__device__ __half g_f1f[T1K * Aa * Hh];
__device__ __half g_f2f[T1K * Hh * Aa];
__device__ __half g_h1f[T1K * M1 * Aa];
__device__ __half g_h2f[T1K * MSZ];
__device__ __half g_sqf[T1K * MSZ];
__device__ __half g_Wgh[NG_PAD * Hh];
__device__ __half g_Wah[NA_PAD * Hh];
__device__ __half g_Ygh[(long)MG * NG_PAD];
__device__ __half g_Yah[(long)M1 * NA_PAD];
__device__ float g_rwT[(long)Nn * T1K * SCn * 300];
__device__ float g_aspf[Bb * 3 * COn];
__device__ float g_asp[Bb * COn];
__device__ float g_z[TnK * Bb * 3 * COn];
__device__ float g_vote[Nn * Bb * SCn];

// ---------------------------------------------------------------------------
// helpers
// ---------------------------------------------------------------------------
__device__ __forceinline__ void mma_fp16(float* c, const uint32_t* a, const uint32_t* b)
{
    asm volatile(
        "mma.sync.aligned.m16n8k16.row.col.f32.f16.f16.f32 "
        "{%0,%1,%2,%3}, {%4,%5,%6,%7}, {%8,%9}, {%0,%1,%2,%3};"
        : "+f"(c[0]), "+f"(c[1]), "+f"(c[2]), "+f"(c[3])
        : "r"(a[0]), "r"(a[1]), "r"(a[2]), "r"(a[3]), "r"(b[0]), "r"(b[1]));
}

__device__ __forceinline__ void ldsm_x4(uint32_t* r, uint32_t addr)
{
    asm volatile("ldmatrix.sync.aligned.m8n8.x4.shared.b16 {%0,%1,%2,%3}, [%4];"
                 : "=r"(r[0]), "=r"(r[1]), "=r"(r[2]), "=r"(r[3]) : "r"(addr));
}

__device__ __forceinline__ void ldsm_x2(uint32_t* r, uint32_t addr)
{
    asm volatile("ldmatrix.sync.aligned.m8n8.x2.shared.b16 {%0,%1}, [%2];"
                 : "=r"(r[0]), "=r"(r[1]) : "r"(addr));
}

__device__ __forceinline__ void cp16(void* sdst, const void* gsrc)
{
    uint32_t s = (uint32_t)__cvta_generic_to_shared(sdst);
    asm volatile("cp.async.cg.shared.global [%0], [%1], 16;" :: "r"(s), "l"(gsrc));
}
#define CP_COMMIT() asm volatile("cp.async.commit_group;" ::: "memory")
#define CP_WAIT0()  asm volatile("cp.async.wait_group 0;" ::: "memory")
#define CP_WAIT1()  asm volatile("cp.async.wait_group 1;" ::: "memory")
#define CP_WAIT2()  asm volatile("cp.async.wait_group 2;" ::: "memory")

// KC=32, RSTR=40, 4-stage pipeline: 80KB smem, 2 CTA/SM (160KB/SM)
#define KC       32
#define RSTR     40
#define MAT_ELE  (128 * RSTR)           // 5120 halfs
#define STG2_ELE (2 * MAT_ELE)
#define NSTG     4
#define SMEM_CV  (NSTG * STG2_ELE * 2)  // 81920 bytes

// ---------------------------------------------------------------------------
// GEMM core — ldmatrix fragments, 4-stage cp.async pipeline (R14 base)
// ---------------------------------------------------------------------------
template<int BIASRELU>
__device__ __forceinline__ void gemm_body(
    __half* smh, const __half* __restrict__ A, const __half* __restrict__ B,
    int N, int Kd, int m0, int n0,
    const float* __restrict__ bias, __half* __restrict__ Ch, long co)
{
    int tid = threadIdx.x, lane = tid & 31, wid = tid >> 5;
    int wm = wid >> 2, wn = wid & 3;
    int gid = lane >> 2, tig = lane & 3;
    int crow = tid >> 2, cch = (tid & 3) * 8;

    int a_off = (wm * 64 + (lane & 15)) * RSTR + (lane >> 4) * 8;
    int b_off = (wn * 32 + (lane & 7)) * RSTR + ((lane >> 3) & 1) * 8;

    uint32_t smh_s = (uint32_t)__cvta_generic_to_shared(smh);

    auto issue = [&](int c) {
        __half* base = smh + (c % NSTG) * STG2_ELE;
        int k0 = c * KC;
        #pragma unroll
        for (int r = 0; r < 2; r++) {
            int row = crow + r * 64;
            long ga = (long)(m0 + row) * Kd + k0 + cch;
            long gb = (long)(n0 + row) * Kd + k0 + cch;
            int so = row * RSTR + cch;
            cp16(base + so,           A + ga);
            cp16(base + MAT_ELE + so, B + gb);
        }
        CP_COMMIT();
    };

    float acc[4][4][4] = {};
    int nch = Kd / KC;

    issue(0);
    issue(1);
    issue(2);

    for (int c = 0; c < nch; c++) {
        if (c + 1 == nch)      CP_WAIT0();
        else if (c + 2 == nch) CP_WAIT1();
        else                   CP_WAIT2();
        __syncthreads();
        if (c + 3 < nch) issue(c + 3);

        uint32_t As_s = smh_s + (uint32_t)((c % NSTG) * STG2_ELE) * 2u;
        uint32_t Bs_s = As_s + MAT_ELE * 2u;

        #pragma unroll
        for (int kk = 0; kk < KC; kk += 16) {
            uint32_t bf[4][2];
            #pragma unroll
            for (int nt = 0; nt < 4; nt++)
                ldsm_x2(bf[nt], Bs_s + (uint32_t)(b_off + nt * 8 * RSTR + kk) * 2u);
            #pragma unroll
            for (int mt = 0; mt < 4; mt++) {
                uint32_t ah[4];
                ldsm_x4(ah, As_s + (uint32_t)(a_off + mt * 16 * RSTR + kk) * 2u);
                #pragma unroll
                for (int nt = 0; nt < 4; nt++)
                    mma_fp16(acc[mt][nt], ah, bf[nt]);
            }
        }
        // stage reuse distance is 4 chunks; the top-of-loop barrier of c+1
        // orders compute(c) before issue(c+4) into the same stage.
    }

    #pragma unroll
    for (int mt = 0; mt < 4; mt++) {
        long m = m0 + wm * 64 + mt * 16 + gid;
        #pragma unroll
        for (int nt = 0; nt < 4; nt++) {
            int col = n0 + wn * 32 + nt * 8 + tig * 2;
            float v00 = acc[mt][nt][0], v01 = acc[mt][nt][1];
            float v10 = acc[mt][nt][2], v11 = acc[mt][nt][3];
            if (BIASRELU) {
                float b0 = bias[col], b1 = bias[col + 1];
                v00 = fmaxf(v00 + b0, 0.f); v01 = fmaxf(v01 + b1, 0.f);
                v10 = fmaxf(v10 + b0, 0.f); v11 = fmaxf(v11 + b1, 0.f);
            }
            *(__half2*)(Ch + co + m * N + col)       = __floats2half2_rn(v00, v01);
            *(__half2*)(Ch + co + (m + 8) * N + col) = __floats2half2_rn(v10, v11);
        }
    }
}

// fc GEMM (bias+relu), z-batched
__global__ void __launch_bounds__(256, 2)
mma_fc(const __half* __restrict__ A, const __half* __restrict__ B,
       const float* __restrict__ bias, __half* __restrict__ Ch,
       int N, int Kd, long sA, long sW, long sB, long sC)
{
    extern __shared__ __half smh[];
    gemm_body<1>(smh, A + blockIdx.z * sA, B + blockIdx.z * sW,
                 N, Kd, blockIdx.y * 128, blockIdx.x * 128,
                 bias + blockIdx.z * sB, Ch, blockIdx.z * sC);
}

// combined conv GEMM (Yg tiles then Ya tiles), no bias
__global__ void __launch_bounds__(256, 2)
mma_conv(const __half* __restrict__ sq, const __half* __restrict__ Wg,
         const __half* __restrict__ Wa, __half* __restrict__ Yg,
         __half* __restrict__ Ya)
{
    extern __shared__ __half smh[];
    int bid = blockIdx.x;
    if (bid < YG_TILES) {
        gemm_body<0>(smh, sq + (long)MSZ, Wg, NG_PAD, Hh,
                     (bid / 19) * 128, (bid % 19) * 128, nullptr, Yg, 0L);
    } else {
        int b2 = bid - YG_TILES;
        gemm_body<0>(smh, sq, Wa, NA_PAD, Hh,
                     (b2 / 10) * 128, (b2 % 10) * 128, nullptr, Ya, 0L);
    }
}

// ===========================================================================
// prep_all: all operand preparation in one launch (segmented grid)
// ===========================================================================
#define W0 ((long)MSZ / 2)
#define W1 ((long)T1K * Aa * Hh / 2)
#define W2 ((long)T1K * Hh * Aa / 2)
#define W3 ((long)NG_PAD * Hh)
#define W4 ((long)NA_PAD * Hh)
#define W5 ((long)Nn * T1K * SCn * 300)
#define WTOT (W0 + W1 + W2 + W3 + W4 + W5)

__device__ __forceinline__ void decode_kg(int kg, int& K, int& k)
{
    if (kg < 3)      { K = 3; k = kg; }
    else if (kg < 7) { K = 4; k = kg - 3; }
    else             { K = 5; k = kg - 7; }
}

__global__ void prep_all(const float* __restrict__ x,
                         const float* __restrict__ f1w, const float* __restrict__ f2w,
                         const float* __restrict__ c1w3, const float* __restrict__ c1w4,
                         const float* __restrict__ c1w5, const float* __restrict__ c2w3,
                         const float* __restrict__ c2w4, const float* __restrict__ c2w5,
                         const float* __restrict__ c3w3, const float* __restrict__ c3w4,
                         const float* __restrict__ c3w5, const float* __restrict__ rw)
{
    long g = (long)blockIdx.x * 256 + threadIdx.x;
    if (g < W0) {
        long i = g * 2;
        float2 v = *(const float2*)(x + i);
        *(__half2*)(g_xf + i) = __floats2half2_rn(v.x, v.y);
        return;
    }
    g -= W0;
    if (g < W1) {
        long i = g * 2;
        float2 v = *(const float2*)(f1w + i);
        *(__half2*)(g_f1f + i) = __floats2half2_rn(v.x, v.y);
        return;
    }
    g -= W1;
    if (g < W2) {
        long i = g * 2;
        float2 v = *(const float2*)(f2w + i);
        *(__half2*)(g_f2f + i) = __floats2half2_rn(v.x, v.y);
        return;
    }
    g -= W2;
    if (g < W3) {
        int ch = (int)(g / Hh), h = (int)(g % Hh);
        float v = 0.f;
        if (ch < 2400) {
            int kg = ch / 200, r = ch % 200;
            int conv = r / 100, cco = r % 100;
            int K, k; decode_kg(kg, K, k);
            const float* w;
            if (conv == 0) w = (K == 3) ? c1w3 : (K == 4) ? c1w4 : c1w5;
            else           w = (K == 3) ? c2w3 : (K == 4) ? c2w4 : c2w5;
            v = w[(long)cco * Hh * K + h * K + k];
        }
        g_Wgh[g] = __float2half_rn(v);
        return;
    }
    g -= W3;
    if (g < W4) {
        int ch = (int)(g / Hh), h = (int)(g % Hh);
        float v = 0.f;
        if (ch < 1200) {
            int kg = ch / 100, cco = ch % 100;
            int K, k; decode_kg(kg, K, k);
            const float* w = (K == 3) ? c3w3 : (K == 4) ? c3w4 : c3w5;
            v = w[(long)cco * Hh * K + h * K + k];
        }
        g_Wah[g] = __float2half_rn(v);
        return;
    }
    g -= W4;
    if (g < W5) {
        int c = (int)(g % 300);
        long row = g / 300;
        int s = (int)(row % 12);
        long ni = row / 12;
        g_rwT[g] = rw[(ni * 300 + c) * 12 + s];
    }
}

// ===========================================================================
// squash: vectorized, 4 elems/thread (lower regs -> higher occupancy)
// ===========================================================================
__global__ void squash_kernel()
{
    long i = ((long)blockIdx.x * 256 + threadIdx.x) * 4;
    if (i >= MSZ) return;
    float v[6][4];
    #pragma unroll
    for (int j = 0; j < 6; j++) {
        int src = (j == 0) ? 5 : j - 1;
        uint2 p = *(const uint2*)(g_h2f + (long)src * MSZ + i);
        const __half2* hp = (const __half2*)&p;
        #pragma unroll
        for (int q = 0; q < 2; q++) {
            float2 f = __half22float2(hp[q]);
            v[j][q * 2] = f.x; v[j][q * 2 + 1] = f.y;
        }
    }
    #pragma unroll
    for (int e = 0; e < 4; e++) {
        float sq = 1e-16f;
        #pragma unroll
        for (int j = 0; j < 6; j++) sq += v[j][e] * v[j][e];
        float sc = sqrtf(sq) / (1.f + sq);
        #pragma unroll
        for (int j = 0; j < 6; j++) v[j][e] *= sc;
    }
    #pragma unroll
    for (int j = 0; j < 6; j++) {
        uint2 p;
        __half2* hp = (__half2*)&p;
        #pragma unroll
        for (int q = 0; q < 2; q++)
            hp[q] = __floats2half2_rn(v[j][q * 2], v[j][q * 2 + 1]);
        *(uint2*)(g_sqf + (long)j * MSZ + i) = p;
    }
}

// ===========================================================================
// Fused aspect epilogue + fca
// ===========================================================================
__global__ void aspect_fca(const float* __restrict__ b3, const float* __restrict__ b4,
                           const float* __restrict__ b5,
                           const float* __restrict__ fw, const float* __restrict__ fb)
{
    __shared__ float red[4 * 300];
    __shared__ float aspf_s[300];
    int b = blockIdx.x, t = threadIdx.x;

    if (t < 600) {
        int lg = t / 150, r = t % 150;
        int g = r / 50, co0 = (r % 50) * 2;
        int K = 3 + g;
        int base = (g == 0) ? 0 : (g == 1) ? 3 : 7;
        int pad = K - 2;
        const float* bias = (g == 0) ? b3 : (g == 1) ? b4 : b5;
        float bb0 = bias[co0], bb1 = bias[co0 + 1];
        int Lout = 125 + K;
        int l0 = lg * 33, l1 = min(Lout, l0 + 33);
        float best0 = 0.f, best1 = 0.f;
        for (int l = l0; l < l1; l++) {
            float s0 = bb0, s1 = bb1;
            #pragma unroll 5
            for (int k = 0; k < K; k++) {
                int ss = l + k - pad;
                if (ss >= 0 && ss < Ss) {
                    __half2 h = *(const __half2*)(g_Yah + ((long)b * Ss + ss) * NA_PAD + (base + k) * 100 + co0);
                    float2 f = __half22float2(h);
                    s0 += f.x; s1 += f.y;
                }
            }
            best0 = fmaxf(best0, s0);
            best1 = fmaxf(best1, s1);
        }
        red[lg * 300 + g * 100 + co0]     = best0;
        red[lg * 300 + g * 100 + co0 + 1] = best1;
    }
    __syncthreads();
    if (t < 300) {
        float m = fmaxf(fmaxf(red[t], red[300 + t]), fmaxf(red[600 + t], red[900 + t]));
        aspf_s[t] = m;
        g_aspf[b * 300 + t] = m;
    }
    __syncthreads();
    if (t < COn) {
        float s = fb[t];
        for (int c = 0; c < 300; c++) s += aspf_s[c] * fw[t * 300 + c];
        g_asp[b * COn + t] = s;
    }
}

// ===========================================================================
// Gated epilogue
// ===========================================================================
__global__ void gated_epi(const float* __restrict__ b13, const float* __restrict__ b14,
                          const float* __restrict__ b15, const float* __restrict__ b23,
                          const float* __restrict__ b24, const float* __restrict__ b25)
{
    __shared__ float red[4 * 300];
    int i = blockIdx.x, t = threadIdx.x;
    int b = i & 63;

    if (t < 600) {
        int lg = t / 150, r = t % 150;
        int g = r / 50, co0 = (r % 50) * 2;
        int K = 3 + g;
        int base = (g == 0) ? 0 : (g == 1) ? 3 : 7;
        const float* bias1 = (g == 0) ? b13 : (g == 1) ? b14 : b15;
        const float* bias2 = (g == 0) ? b23 : (g == 1) ? b24 : b25;
        float c1b0 = bias1[co0], c1b1 = bias1[co0 + 1];
        float c2b0 = bias2[co0]     + g_asp[b * COn + co0];
        float c2b1 = bias2[co0 + 1] + g_asp[b * COn + co0 + 1];
        int Lout = Ss - K + 1;
        int l0 = lg * 32, l1 = min(Lout, l0 + 32);
        float best0 = -1e30f, best1 = -1e30f;
        for (int l = l0; l < l1; l++) {
            float s10 = c1b0, s11 = c1b1, s20 = c2b0, s21 = c2b1;
            #pragma unroll 5
            for (int k = 0; k < K; k++) {
                long row = (long)i * Ss + l + k;
                __half2 ha = *(const __half2*)(g_Ygh + row * NG_PAD + (base + k) * 200 + co0);
                __half2 hb = *(const __half2*)(g_Ygh + row * NG_PAD + (base + k) * 200 + 100 + co0);
                float2 fa = __half22float2(ha);
                float2 fbv = __half22float2(hb);
                s10 += fa.x;  s11 += fa.y;
                s20 += fbv.x; s21 += fbv.y;
            }
            float v0 = tanhf(s10) * fmaxf(s20, 0.f);
            float v1 = tanhf(s11) * fmaxf(s21, 0.f);
            best0 = fmaxf(best0, v0);
            best1 = fmaxf(best1, v1);
        }
        red[lg * 300 + g * 100 + co0]     = best0;
        red[lg * 300 + g * 100 + co0 + 1] = best1;
    }
    __syncthreads();
    if (t < 300)
        g_z[i * 300 + t] = fmaxf(fmaxf(red[t], red[300 + t]), fmaxf(red[600 + t], red[900 + t]));
}

// ===========================================================================
// Fused priors + routing
// ===========================================================================
__global__ void priors_routing()
{
    __shared__ float cap[1800];
    __shared__ float pri[72];
    int b = blockIdx.x, n = blockIdx.y, tid = threadIdx.x;
    for (int idx = tid; idx < 1800; idx += 128) {
        int i = idx / 300, c = idx % 300;
        cap[idx] = (i == 0) ? g_aspf[b * 300 + c] : g_z[((i - 1) * Bb + b) * 300 + c];
    }
    __syncthreads();
    if (tid < 72) {
        int i = tid / 12, s = tid % 12;
        const float4* rp = (const float4*)(g_rwT + ((long)(n * 6 + i) * 12 + s) * 300);
        const float* cp = &cap[i * 300];
        float acc = 0.f;
        #pragma unroll 5
        for (int c4 = 0; c4 < 75; c4++) {
            float4 r4 = rp[c4];
            acc += cp[c4 * 4]     * r4.x + cp[c4 * 4 + 1] * r4.y
                 + cp[c4 * 4 + 2] * r4.z + cp[c4 * 4 + 3] * r4.w;
        }
        pri[tid] = acc;
    }
    __syncthreads();
    if (tid == 0) {
        float logits[6] = {0, 0, 0, 0, 0, 0};
        float vote[12];
        #pragma unroll
        for (int it = 0; it < 3; it++) {
            float mx = logits[0];
            #pragma unroll
            for (int i = 1; i < 6; i++) mx = fmaxf(mx, logits[i]);
            float e[6], se = 0.f;
            #pragma unroll
            for (int i = 0; i < 6; i++) { e[i] = expf(logits[i] - mx); se += e[i]; }
            float inv = 1.f / se;
            #pragma unroll
            for (int s = 0; s < 12; s++) {
                float v = 0.f;
                #pragma unroll
                for (int i = 0; i < 6; i++) v += e[i] * pri[i * 12 + s];
                vote[s] = v * inv;
            }
            if (it < 2) {
                float sq = 1e-16f;
                #pragma unroll
                for (int s = 0; s < 12; s++) sq += vote[s] * vote[s];
                float sc = sqrtf(sq) / (1.f + sq);
                #pragma unroll
                for (int i = 0; i < 6; i++) {
                    float d = 0.f;
                    #pragma unroll
                    for (int s = 0; s < 12; s++) d += pri[i * 12 + s] * vote[s];
                    logits[i] += d * sc;
                }
            }
        }
        #pragma unroll
        for (int s = 0; s < 12; s++)
            g_vote[(n * Bb + b) * 12 + s] = vote[s];
    }
}

// ===========================================================================
// final residual add, float4 vectorized
// ===========================================================================
__global__ void final_kernel(const float* __restrict__ x, float* __restrict__ out)
{
    long idx = ((long)blockIdx.x * 256 + threadIdx.x) * 4;
    if (idx >= MSZ) return;
    float4 xv = *(const float4*)(x + idx);
    uint2 hp = *(const uint2*)(g_h2f + (long)5 * MSZ + idx);
    const __half2* hh = (const __half2*)&hp;
    float2 h0 = __half22float2(hh[0]);
    float2 h1 = __half22float2(hh[1]);
    int b = (int)(idx / (Ss * Hh));
    int h = (int)(idx % Hh);
    float4 vv = *(const float4*)(g_vote + b * Hh + h);
    float4 o;
    o.x = xv.x + h0.x + vv.x;
    o.y = xv.y + h0.y + vv.y;
    o.z = xv.z + h1.x + vv.z;
    o.w = xv.w + h1.y + vv.w;
    *(float4*)(out + idx) = o;
}

// ===========================================================================
extern "C" void kernel_launch(void* const* d_in, const int* in_sizes, int n_in,
                              void* d_out, int out_size)
{
    const float* x     = (const float*)d_in[0];
    const float* fc1_w = (const float*)d_in[1];
    const float* fc1_b = (const float*)d_in[2];
    const float* fc2_w = (const float*)d_in[3];
    const float* fc2_b = (const float*)d_in[4];
    const float* c1_w3 = (const float*)d_in[5];
    const float* c1_b3 = (const float*)d_in[6];
    const float* c1_w4 = (const float*)d_in[7];
    const float* c1_b4 = (const float*)d_in[8];
    const float* c1_w5 = (const float*)d_in[9];
    const float* c1_b5 = (const float*)d_in[10];
    const float* c2_w3 = (const float*)d_in[11];
    const float* c2_b3 = (const float*)d_in[12];
    const float* c2_w4 = (const float*)d_in[13];
    const float* c2_b4 = (const float*)d_in[14];
    const float* c2_w5 = (const float*)d_in[15];
    const float* c2_b5 = (const float*)d_in[16];
    const float* c3_w3 = (const float*)d_in[17];
    const float* c3_b3 = (const float*)d_in[18];
    const float* c3_w4 = (const float*)d_in[19];
    const float* c3_b4 = (const float*)d_in[20];
    const float* c3_w5 = (const float*)d_in[21];
    const float* c3_b5 = (const float*)d_in[22];
    const float* fca_w = (const float*)d_in[23];
    const float* fca_b = (const float*)d_in[24];
    const float* rw    = (const float*)d_in[25];
    float* out = (float*)d_out;

    __half *p_xf, *p_f1f, *p_f2f, *p_h1f, *p_h2f, *p_sqf, *p_Wgh, *p_Wah, *p_Ygh, *p_Yah;
    cudaGetSymbolAddress((void**)&p_xf,  g_xf);
    cudaGetSymbolAddress((void**)&p_f1f, g_f1f);
    cudaGetSymbolAddress((void**)&p_f2f, g_f2f);
    cudaGetSymbolAddress((void**)&p_h1f, g_h1f);
    cudaGetSymbolAddress((void**)&p_h2f, g_h2f);
    cudaGetSymbolAddress((void**)&p_sqf, g_sqf);
    cudaGetSymbolAddress((void**)&p_Wgh, g_Wgh);
    cudaGetSymbolAddress((void**)&p_Wah, g_Wah);
    cudaGetSymbolAddress((void**)&p_Ygh, g_Ygh);
    cudaGetSymbolAddress((void**)&p_Yah, g_Yah);

    cudaFuncSetAttribute(mma_fc,   cudaFuncAttributeMaxDynamicSharedMemorySize, SMEM_CV);
    cudaFuncSetAttribute(mma_conv, cudaFuncAttributeMaxDynamicSharedMemorySize, SMEM_CV);

    // 0) all operand prep in one launch
    prep_all<<<(int)((WTOT + 255) / 256), 256>>>(
        x, fc1_w, fc2_w, c1_w3, c1_w4, c1_w5, c2_w3, c2_w4, c2_w5,
        c3_w3, c3_w4, c3_w5, rw);

    // 1) h1 = relu(x @ fc1_w^T + b) -> fp16
    mma_fc<<<dim3(Aa / 128, M1 / 128, T1K), 256, SMEM_CV>>>(
        p_xf, p_f1f, fc1_b, p_h1f,
        Aa, Hh, 0L, (long)Aa * Hh, (long)Aa, (long)M1 * Aa);

    // 2) h2 = relu(h1 @ fc2_w^T + b) -> fp16
    mma_fc<<<dim3(Hh / 128, M1 / 128, T1K), 256, SMEM_CV>>>(
        p_h1f, p_f2f, fc2_b, p_h2f,
        Hh, Aa, (long)M1 * Aa, (long)Hh * Aa, (long)Hh, (long)M1 * Hh);

    // 3) squash -> fp16 capsules
    squash_kernel<<<(MSZ / 4 + 255) / 256, 256>>>();

    // 4) combined conv GEMMs (Yg + Ya in one launch)
    mma_conv<<<YG_TILES + YA_TILES, 256, SMEM_CV>>>(p_sqf, p_Wgh, p_Wah, p_Ygh, p_Yah);

    // 5) epilogues
    aspect_fca<<<Bb, 640>>>(c3_b3, c3_b4, c3_b5, fca_w, fca_b);
    gated_epi<<<TnK * Bb, 640>>>(c1_b3, c1_b4, c1_b5, c2_b3, c2_b4, c2_b5);

    // 6) fused priors + routing
    priors_routing<<<dim3(Bb, Nn), 128>>>();

    // 7) residual add
    final_kernel<<<(MSZ / 4 + 255) / 256, 256>>>(x, out);
}